// round 1
// baseline (speedup 1.0000x reference)
#include <cuda_runtime.h>

#define EPSF 1e-6f
constexpr int B_ = 8;      // batch
constexpr int C_ = 512;    // channels (= D)
constexpr int N_ = 4096;   // spatial H*W
constexpr int R_ = 64;     // bases rank

// ---------------- scratch (device globals; no allocation) ----------------
__device__ float g_h1  [(size_t)B_*C_*N_];   // relu(lower conv)   64 MB
__device__ float g_ham [(size_t)B_*C_*N_];   // bases @ coef^T     64 MB
__device__ float g_h2  [(size_t)B_*C_*N_];   // relu(cheese)       64 MB
__device__ float g_bases[(size_t)B_*C_*R_];
__device__ float g_coef [(size_t)B_*N_*R_];
__device__ float g_xtb  [(size_t)B_*N_*R_];
__device__ float g_btb  [(size_t)B_*R_*R_];
__device__ float g_ctc_part[(size_t)16*B_*R_*R_];
__device__ float g_xc_part [(size_t)8*B_*C_*R_];

// ---------------- l2 normalize bases0 over D ----------------
__global__ void k_l2norm(const float* __restrict__ b0)
{
    int b = blockIdx.x >> 6, r = blockIdx.x & 63;
    const float* src = b0 + (size_t)b*C_*R_ + r;
    float ss = 0.f;
    for (int d = threadIdx.x; d < C_; d += 128) { float v = src[(size_t)d*R_]; ss += v*v; }
    __shared__ float red[128];
    red[threadIdx.x] = ss; __syncthreads();
    for (int s = 64; s > 0; s >>= 1) {
        if (threadIdx.x < s) red[threadIdx.x] += red[threadIdx.x + s];
        __syncthreads();
    }
    float inv = 1.f / fmaxf(sqrtf(red[0]), 1e-12f);
    float* dst = g_bases + (size_t)b*C_*R_ + r;
    for (int d = threadIdx.x; d < C_; d += 128) dst[(size_t)d*R_] = src[(size_t)d*R_] * inv;
}

// ---------------- big SGEMM: Y[b] = epilogue(W @ X[b]) ----------------
// W: [512,512] row-major, X: [B,512,4096], tiles 128x128x8, 256 thr, 8x8 micro
// SEL: 0 = x -> g_h1 (+bias, relu) | 1 = g_ham -> g_h2 (+bias, relu)
//      2 = g_h2 -> dout, relu(ch*acc + cs*shortcut)
template<int SEL>
__global__ __launch_bounds__(256) void k_gemm512(
    const float* __restrict__ W, const float* __restrict__ xin,
    const float* __restrict__ bias, const float* __restrict__ shortcut,
    const float* __restrict__ p_ham, const float* __restrict__ p_sc,
    float* __restrict__ dout)
{
    const float* X = (SEL == 0) ? xin : (SEL == 1) ? g_ham : g_h2;
    float*       Y = (SEL == 0) ? g_h1 : (SEL == 1) ? g_h2 : dout;

    int b  = blockIdx.z;
    int m0 = blockIdx.y * 128;
    int n0 = blockIdx.x * 128;
    const float* Xb = X + (size_t)b*C_*N_;

    __shared__ float As[8][128];
    __shared__ float Bs[8][132];

    int t  = threadIdx.x;
    int tx = t & 15, ty = t >> 4;
    float acc[8][8];
#pragma unroll
    for (int i = 0; i < 8; i++)
#pragma unroll
        for (int j = 0; j < 8; j++) acc[i][j] = 0.f;

    int arow = t >> 1, acol = (t & 1) * 4;
    int brow = t >> 5, bcol = (t & 31) * 4;
    const float* Aptr = W  + (size_t)(m0 + arow)*C_ + acol;
    const float* Bptr = Xb + (size_t)brow*N_ + n0 + bcol;

    for (int k0 = 0; k0 < C_; k0 += 8) {
        float4 av = *(const float4*)(Aptr + k0);
        float4 bv = *(const float4*)(Bptr + (size_t)k0*N_);
        __syncthreads();
        As[acol+0][arow] = av.x; As[acol+1][arow] = av.y;
        As[acol+2][arow] = av.z; As[acol+3][arow] = av.w;
        *(float4*)&Bs[brow][bcol] = bv;
        __syncthreads();
#pragma unroll
        for (int k = 0; k < 8; k++) {
            float4 a0 = *(float4*)&As[k][ty*8], a1 = *(float4*)&As[k][ty*8+4];
            float4 b0 = *(float4*)&Bs[k][tx*8], b1 = *(float4*)&Bs[k][tx*8+4];
            float ar[8] = {a0.x,a0.y,a0.z,a0.w,a1.x,a1.y,a1.z,a1.w};
            float br[8] = {b0.x,b0.y,b0.z,b0.w,b1.x,b1.y,b1.z,b1.w};
#pragma unroll
            for (int i = 0; i < 8; i++)
#pragma unroll
                for (int j = 0; j < 8; j++) acc[i][j] += ar[i]*br[j];
        }
    }

    float ch = 1.f, cs = 1.f;
    if (SEL == 2) { ch = p_ham[0]; cs = p_sc[0]; }
#pragma unroll
    for (int i = 0; i < 8; i++) {
        int m = m0 + ty*8 + i;
        float* yp = Y + (size_t)b*C_*N_ + (size_t)m*N_ + n0 + tx*8;
        if (SEL != 2) {
            float bvv = bias[m];
            float4 o0, o1;
            o0.x = fmaxf(acc[i][0]+bvv, 0.f); o0.y = fmaxf(acc[i][1]+bvv, 0.f);
            o0.z = fmaxf(acc[i][2]+bvv, 0.f); o0.w = fmaxf(acc[i][3]+bvv, 0.f);
            o1.x = fmaxf(acc[i][4]+bvv, 0.f); o1.y = fmaxf(acc[i][5]+bvv, 0.f);
            o1.z = fmaxf(acc[i][6]+bvv, 0.f); o1.w = fmaxf(acc[i][7]+bvv, 0.f);
            *(float4*)yp = o0; *(float4*)(yp+4) = o1;
        } else {
            const float* sp = shortcut + (size_t)b*C_*N_ + (size_t)m*N_ + n0 + tx*8;
            float4 s0 = *(const float4*)sp, s1 = *(const float4*)(sp+4);
            float4 o0, o1;
            o0.x = fmaxf(ch*acc[i][0] + cs*s0.x, 0.f);
            o0.y = fmaxf(ch*acc[i][1] + cs*s0.y, 0.f);
            o0.z = fmaxf(ch*acc[i][2] + cs*s0.z, 0.f);
            o0.w = fmaxf(ch*acc[i][3] + cs*s0.w, 0.f);
            o1.x = fmaxf(ch*acc[i][4] + cs*s1.x, 0.f);
            o1.y = fmaxf(ch*acc[i][5] + cs*s1.y, 0.f);
            o1.z = fmaxf(ch*acc[i][6] + cs*s1.z, 0.f);
            o1.w = fmaxf(ch*acc[i][7] + cs*s1.w, 0.f);
            *(float4*)yp = o0; *(float4*)(yp+4) = o1;
        }
    }
}

// ---------------- xtb[b,n,r] = sum_d h1[b,d,n] * bases[b,d,r] ----------------
// tiles: 128 n x 64 r, K=16 per step; 256 thr, 8x4 micro
__global__ __launch_bounds__(256) void k_xtb()
{
    int n0 = blockIdx.x * 128, b = blockIdx.y;
    const float* xb = g_h1    + (size_t)b*C_*N_;
    const float* bp = g_bases + (size_t)b*C_*R_;
    __shared__ float xs[16][128];
    __shared__ float bs[16][64];
    int t = threadIdx.x;
    int tn = t & 15, tr = t >> 4;
    int lrow = t >> 4, xcol = (t & 15) * 8, bcol = (t & 15) * 4;
    float acc[8][4];
#pragma unroll
    for (int i = 0; i < 8; i++)
#pragma unroll
        for (int j = 0; j < 4; j++) acc[i][j] = 0.f;

    for (int d0 = 0; d0 < C_; d0 += 16) {
        float4 x0 = *(const float4*)(xb + (size_t)(d0+lrow)*N_ + n0 + xcol);
        float4 x1 = *(const float4*)(xb + (size_t)(d0+lrow)*N_ + n0 + xcol + 4);
        float4 b0 = *(const float4*)(bp + (size_t)(d0+lrow)*R_ + bcol);
        __syncthreads();
        *(float4*)&xs[lrow][xcol]   = x0;
        *(float4*)&xs[lrow][xcol+4] = x1;
        *(float4*)&bs[lrow][bcol]   = b0;
        __syncthreads();
#pragma unroll
        for (int k = 0; k < 16; k++) {
            float4 a0 = *(float4*)&xs[k][tn*8], a1 = *(float4*)&xs[k][tn*8+4];
            float4 bv = *(float4*)&bs[k][tr*4];
            float av[8] = {a0.x,a0.y,a0.z,a0.w,a1.x,a1.y,a1.z,a1.w};
            float br[4] = {bv.x,bv.y,bv.z,bv.w};
#pragma unroll
            for (int i = 0; i < 8; i++)
#pragma unroll
                for (int j = 0; j < 4; j++) acc[i][j] += av[i]*br[j];
        }
    }
    float* op = g_xtb + ((size_t)b*N_ + n0 + tn*8)*R_ + tr*4;
#pragma unroll
    for (int i = 0; i < 8; i++) {
        float4 o = {acc[i][0], acc[i][1], acc[i][2], acc[i][3]};
        *(float4*)(op + (size_t)i*R_) = o;
    }
}

// ---------------- coef init: softmax over r of xtb ----------------
__global__ void k_softmax()
{
    int row  = blockIdx.x * 8 + (threadIdx.x >> 5);
    int lane = threadIdx.x & 31;
    const float* xp = g_xtb + (size_t)row*R_;
    float v0 = xp[lane], v1 = xp[lane+32];
    float m = fmaxf(v0, v1);
#pragma unroll
    for (int o = 16; o; o >>= 1) m = fmaxf(m, __shfl_xor_sync(0xffffffffu, m, o));
    float e0 = __expf(v0 - m), e1 = __expf(v1 - m);
    float s = e0 + e1;
#pragma unroll
    for (int o = 16; o; o >>= 1) s += __shfl_xor_sync(0xffffffffu, s, o);
    float inv = 1.f / s;
    float* op = g_coef + (size_t)row*R_;
    op[lane] = e0*inv; op[lane+32] = e1*inv;
}

// ---------------- btb[b,r,s] = sum_d bases[b,d,r]*bases[b,d,s] ----------------
__global__ __launch_bounds__(256) void k_btb()
{
    int b = blockIdx.x, g = blockIdx.y;
    const float* bp = g_bases + (size_t)b*C_*R_;
    __shared__ float sh[32][64];
    int t = threadIdx.x;
    int r = g*4 + (t >> 6), s = t & 63;
    float acc = 0.f;
    for (int d0 = 0; d0 < C_; d0 += 32) {
        __syncthreads();
        for (int i = t; i < 2048; i += 256) sh[i>>6][i&63] = bp[(size_t)d0*R_ + i];
        __syncthreads();
#pragma unroll
        for (int d = 0; d < 32; d++) acc += sh[d][r]*sh[d][s];
    }
    g_btb[((size_t)b*R_ + r)*R_ + s] = acc;
}

// ---------------- coef *= xtb / (coef @ btb + eps), in-place ----------------
__global__ __launch_bounds__(256) void k_coef_update()
{
    int b = blockIdx.y, n0 = blockIdx.x * 32;
    __shared__ float bt[64][64];
    __shared__ float cr[32][64];
    int t = threadIdx.x;
    const float* bp = g_btb + (size_t)b*R_*R_;
    for (int i = t; i < 4096; i += 256) bt[i>>6][i&63] = bp[i];
    const float* cp = g_coef + ((size_t)b*N_ + n0)*R_;
    for (int i = t; i < 2048; i += 256) cr[i>>6][i&63] = cp[i];
    __syncthreads();
    int nl = t >> 3, r0 = (t & 7) * 8;
    float acc[8] = {0,0,0,0,0,0,0,0};
#pragma unroll 8
    for (int s = 0; s < 64; s++) {
        float c = cr[nl][s];
        float4 b0 = *(float4*)&bt[s][r0], b1 = *(float4*)&bt[s][r0+4];
        acc[0] += c*b0.x; acc[1] += c*b0.y; acc[2] += c*b0.z; acc[3] += c*b0.w;
        acc[4] += c*b1.x; acc[5] += c*b1.y; acc[6] += c*b1.z; acc[7] += c*b1.w;
    }
    const float* xp = g_xtb + ((size_t)b*N_ + n0 + nl)*R_ + r0;
    float* op = g_coef + ((size_t)b*N_ + n0 + nl)*R_ + r0;
#pragma unroll
    for (int j = 0; j < 8; j++) op[j] = cr[nl][r0+j] * xp[j] / (acc[j] + EPSF);
}

// ---------------- xc partials: split-K over n (8 splits x 512) ----------------
__global__ __launch_bounds__(256) void k_xc_part()
{
    int m0 = blockIdx.x * 128, b = blockIdx.y, sp = blockIdx.z;
    const float* xb = g_h1   + (size_t)b*C_*N_ + sp*512;
    const float* cp = g_coef + ((size_t)b*N_ + sp*512)*R_;
    __shared__ float xs[16][128];
    __shared__ float cs[16][64];
    int t = threadIdx.x;
    int td = t & 15, tr = t >> 4;
    int lrow = t >> 1, lnc = (t & 1) * 8;
    int crow = t >> 4, ccol = (t & 15) * 4;
    float acc[8][4];
#pragma unroll
    for (int i = 0; i < 8; i++)
#pragma unroll
        for (int j = 0; j < 4; j++) acc[i][j] = 0.f;

    for (int n0 = 0; n0 < 512; n0 += 16) {
        float4 x0 = *(const float4*)(xb + (size_t)(m0+lrow)*N_ + n0 + lnc);
        float4 x1 = *(const float4*)(xb + (size_t)(m0+lrow)*N_ + n0 + lnc + 4);
        float4 c0 = *(const float4*)(cp + (size_t)(n0+crow)*R_ + ccol);
        __syncthreads();
        xs[lnc+0][lrow] = x0.x; xs[lnc+1][lrow] = x0.y;
        xs[lnc+2][lrow] = x0.z; xs[lnc+3][lrow] = x0.w;
        xs[lnc+4][lrow] = x1.x; xs[lnc+5][lrow] = x1.y;
        xs[lnc+6][lrow] = x1.z; xs[lnc+7][lrow] = x1.w;
        *(float4*)&cs[crow][ccol] = c0;
        __syncthreads();
#pragma unroll
        for (int k = 0; k < 16; k++) {
            float4 a0 = *(float4*)&xs[k][td*8], a1 = *(float4*)&xs[k][td*8+4];
            float4 cv = *(float4*)&cs[k][tr*4];
            float av[8] = {a0.x,a0.y,a0.z,a0.w,a1.x,a1.y,a1.z,a1.w};
            float cvv[4] = {cv.x,cv.y,cv.z,cv.w};
#pragma unroll
            for (int i = 0; i < 8; i++)
#pragma unroll
                for (int j = 0; j < 4; j++) acc[i][j] += av[i]*cvv[j];
        }
    }
#pragma unroll
    for (int i = 0; i < 8; i++) {
        float* op = g_xc_part + ((size_t)(sp*8 + b)*C_ + m0 + td*8 + i)*R_ + tr*4;
        float4 o = {acc[i][0], acc[i][1], acc[i][2], acc[i][3]};
        *(float4*)op = o;
    }
}

// ---------------- ctc partials: split over n (16 splits x 256) ----------------
__global__ __launch_bounds__(256) void k_ctc_part()
{
    int b = blockIdx.x, sp = blockIdx.y;
    const float* cp = g_coef + ((size_t)b*N_ + sp*256)*R_;
    __shared__ float sh[32][64];
    int t = threadIdx.x;
    int rg = t >> 4, cg = t & 15;
    float acc[4][4];
#pragma unroll
    for (int i = 0; i < 4; i++)
#pragma unroll
        for (int j = 0; j < 4; j++) acc[i][j] = 0.f;

    for (int n0 = 0; n0 < 256; n0 += 32) {
        __syncthreads();
        for (int i = t; i < 2048; i += 256) sh[i>>6][i&63] = cp[(size_t)n0*R_ + i];
        __syncthreads();
#pragma unroll 4
        for (int n = 0; n < 32; n++) {
            float4 a = *(float4*)&sh[n][rg*4];
            float4 c = *(float4*)&sh[n][cg*4];
            float av[4] = {a.x,a.y,a.z,a.w}, cv[4] = {c.x,c.y,c.z,c.w};
#pragma unroll
            for (int i = 0; i < 4; i++)
#pragma unroll
                for (int j = 0; j < 4; j++) acc[i][j] += av[i]*cv[j];
        }
    }
    float* op = g_ctc_part + ((size_t)(sp*8 + b)*R_ + rg*4)*R_ + cg*4;
#pragma unroll
    for (int i = 0; i < 4; i++) {
        float4 o = {acc[i][0], acc[i][1], acc[i][2], acc[i][3]};
        *(float4*)(op + (size_t)i*R_) = o;
    }
}

// ---------------- bases *= xc / (bases @ ctc + eps), in-place ----------------
__global__ __launch_bounds__(256) void k_bases_update()
{
    int b = blockIdx.x, d0 = blockIdx.y * 64;
    __shared__ float ct[64][64];
    __shared__ float br[64][64];
    int t = threadIdx.x;
    for (int i = t; i < 4096; i += 256) {
        float s = 0.f;
#pragma unroll
        for (int p = 0; p < 16; p++) s += g_ctc_part[(size_t)(p*8 + b)*4096 + i];
        ct[i>>6][i&63] = s;
    }
    const float* bp = g_bases + ((size_t)b*C_ + d0)*R_;
    for (int i = t; i < 4096; i += 256) br[i>>6][i&63] = bp[i];
    __syncthreads();
    int dl = t >> 2, r0 = (t & 3) * 16;
    float acc[16];
#pragma unroll
    for (int j = 0; j < 16; j++) acc[j] = 0.f;
#pragma unroll 4
    for (int s = 0; s < 64; s++) {
        float bv = br[dl][s];
#pragma unroll
        for (int j4 = 0; j4 < 16; j4 += 4) {
            float4 v = *(float4*)&ct[s][r0 + j4];
            acc[j4+0] += bv*v.x; acc[j4+1] += bv*v.y;
            acc[j4+2] += bv*v.z; acc[j4+3] += bv*v.w;
        }
    }
    float xcs[16];
#pragma unroll
    for (int j = 0; j < 16; j++) xcs[j] = 0.f;
#pragma unroll
    for (int p = 0; p < 8; p++) {
        const float* xp = g_xc_part + ((size_t)(p*8 + b)*C_ + d0 + dl)*R_ + r0;
#pragma unroll
        for (int j4 = 0; j4 < 16; j4 += 4) {
            float4 v = *(const float4*)(xp + j4);
            xcs[j4+0] += v.x; xcs[j4+1] += v.y; xcs[j4+2] += v.z; xcs[j4+3] += v.w;
        }
    }
    float* op = g_bases + ((size_t)b*C_ + d0 + dl)*R_ + r0;
#pragma unroll
    for (int j = 0; j < 16; j++) op[j] = br[dl][r0+j] * xcs[j] / (acc[j] + EPSF);
}

// ---------------- ham[b,d,n] = sum_r bases[b,d,r]*coef[b,n,r] ----------------
// tiles 64d x 64n, K=64 fully resident; 256 thr, 4x4 micro
__global__ __launch_bounds__(256) void k_ham()
{
    int b = blockIdx.z, d0 = blockIdx.y * 64, n0 = blockIdx.x * 64;
    __shared__ float bs[64][65];
    __shared__ float cs[64][65];
    int t = threadIdx.x;
    const float* bp = g_bases + ((size_t)b*C_ + d0)*R_;
    const float* cp = g_coef  + ((size_t)b*N_ + n0)*R_;
    for (int i = t; i < 4096; i += 256) {
        bs[i>>6][i&63] = bp[i];
        cs[i>>6][i&63] = cp[i];
    }
    __syncthreads();
    int td = t >> 4, tn = t & 15;
    float acc[4][4];
#pragma unroll
    for (int i = 0; i < 4; i++)
#pragma unroll
        for (int j = 0; j < 4; j++) acc[i][j] = 0.f;
#pragma unroll 8
    for (int r = 0; r < 64; r++) {
        float bv[4], cv[4];
#pragma unroll
        for (int i = 0; i < 4; i++) bv[i] = bs[td*4+i][r];
#pragma unroll
        for (int j = 0; j < 4; j++) cv[j] = cs[tn*4+j][r];
#pragma unroll
        for (int i = 0; i < 4; i++)
#pragma unroll
            for (int j = 0; j < 4; j++) acc[i][j] += bv[i]*cv[j];
    }
#pragma unroll
    for (int i = 0; i < 4; i++) {
        float* op = g_ham + (size_t)b*C_*N_ + (size_t)(d0 + td*4 + i)*N_ + n0 + tn*4;
        float4 o = {acc[i][0], acc[i][1], acc[i][2], acc[i][3]};
        *(float4*)op = o;
    }
}

// ---------------- host driver ----------------
extern "C" void kernel_launch(void* const* d_in, const int* in_sizes, int n_in,
                              void* d_out, int out_size)
{
    (void)in_sizes; (void)n_in; (void)out_size;
    const float* x        = (const float*)d_in[0];
    const float* bases0   = (const float*)d_in[1];
    const float* w_lower  = (const float*)d_in[2];
    const float* b_lower  = (const float*)d_in[3];
    const float* w_cheese = (const float*)d_in[4];
    const float* b_cheese = (const float*)d_in[5];
    const float* w_upper  = (const float*)d_in[6];
    const float* c_sc     = (const float*)d_in[7];
    const float* c_ham    = (const float*)d_in[8];
    float* out = (float*)d_out;

    dim3 gg(32, 4, 8);

    k_l2norm<<<512, 128>>>(bases0);
    k_gemm512<0><<<gg, 256>>>(w_lower, x, b_lower, nullptr, nullptr, nullptr, nullptr);

    // coef init: softmax(x^T bases)
    k_xtb<<<dim3(32, 8), 256>>>();
    k_softmax<<<4096, 256>>>();

    for (int it = 0; it < 6; ++it) {
        k_xtb<<<dim3(32, 8), 256>>>();
        k_btb<<<dim3(8, 16), 256>>>();
        k_coef_update<<<dim3(128, 8), 256>>>();
        k_xc_part<<<dim3(4, 8, 8), 256>>>();
        k_ctc_part<<<dim3(8, 16), 256>>>();
        k_bases_update<<<dim3(8, 8), 256>>>();
    }

    // final differentiable coef refinement
    k_xtb<<<dim3(32, 8), 256>>>();
    k_btb<<<dim3(8, 16), 256>>>();
    k_coef_update<<<dim3(128, 8), 256>>>();

    // reconstruct, cheese, upper + residual + relu
    k_ham<<<dim3(64, 8, 8), 256>>>();
    k_gemm512<1><<<gg, 256>>>(w_cheese, nullptr, b_cheese, nullptr, nullptr, nullptr, nullptr);
    k_gemm512<2><<<gg, 256>>>(w_upper, nullptr, nullptr, x, c_ham, c_sc, out);
}